// round 9
// baseline (speedup 1.0000x reference)
#include <cuda_runtime.h>
#include <cuda_bf16.h>
#include <cstdint>
#include <math.h>

// ---------------- problem constants ----------------
#define BS_      16
#define LQ_      1000
#define NROWS    (BS_*LQ_)         // 16000
#define EMBED    256
#define NHEADS   8
#define HDIM     32
#define NLOGIT   384               // 256 offset cols + 128 attn-prob cols
#define LV_      13294

__device__ float g_logits[NROWS * NLOGIT];      // off(256) | softmaxed attn(128)
__device__ __nv_bfloat16 g_ahi[NROWS * EMBED];  // A split-hi  [row][k]
__device__ __nv_bfloat16 g_alo[NROWS * EMBED];  // A split-lo
__device__ __nv_bfloat16 g_bhi[NLOGIT * EMBED]; // B^T split-hi [n][k]
__device__ __nv_bfloat16 g_blo[NLOGIT * EMBED]; // B^T split-lo

// ======================= helpers =======================
__device__ __forceinline__ uint32_t smem_u32(const void* p) {
    uint32_t a;
    asm("{ .reg .u64 t; cvta.to.shared.u64 t, %1; cvt.u32.u64 %0, t; }" : "=r"(a) : "l"(p));
    return a;
}

__device__ __forceinline__ void ldsm4(uint32_t& r0, uint32_t& r1, uint32_t& r2, uint32_t& r3,
                                      uint32_t addr) {
    asm volatile("ldmatrix.sync.aligned.m8n8.x4.shared.b16 {%0,%1,%2,%3}, [%4];"
                 : "=r"(r0), "=r"(r1), "=r"(r2), "=r"(r3) : "r"(addr));
}

__device__ __forceinline__ void mma16816(float* c, const uint32_t* a, const uint32_t* b) {
    asm volatile(
        "mma.sync.aligned.m16n8k16.row.col.f32.bf16.bf16.f32 "
        "{%0,%1,%2,%3}, {%4,%5,%6,%7}, {%8,%9}, {%0,%1,%2,%3};"
        : "+f"(c[0]), "+f"(c[1]), "+f"(c[2]), "+f"(c[3])
        : "r"(a[0]), "r"(a[1]), "r"(a[2]), "r"(a[3]), "r"(b[0]), "r"(b[1]));
}

__device__ __forceinline__ uint32_t pack_bf2(__nv_bfloat16 a, __nv_bfloat16 b) {
    return (uint32_t)__bfloat16_as_ushort(a) | ((uint32_t)__bfloat16_as_ushort(b) << 16);
}

// ======================= conversion kernels =======================
__global__ __launch_bounds__(256)
void conv_a_kernel(const float* __restrict__ q)
{
    const size_t i = ((size_t)blockIdx.x * 256 + threadIdx.x) * 8;
    float4 v0 = __ldg(reinterpret_cast<const float4*>(q + i));
    float4 v1 = __ldg(reinterpret_cast<const float4*>(q + i + 4));
    float v[8] = {v0.x, v0.y, v0.z, v0.w, v1.x, v1.y, v1.z, v1.w};
    __nv_bfloat16 hi[8], lo[8];
    #pragma unroll
    for (int j = 0; j < 8; j++) {
        hi[j] = __float2bfloat16(v[j]);
        lo[j] = __float2bfloat16(v[j] - __bfloat162float(hi[j]));
    }
    uint4 uh, ul;
    uh.x = pack_bf2(hi[0], hi[1]); uh.y = pack_bf2(hi[2], hi[3]);
    uh.z = pack_bf2(hi[4], hi[5]); uh.w = pack_bf2(hi[6], hi[7]);
    ul.x = pack_bf2(lo[0], lo[1]); ul.y = pack_bf2(lo[2], lo[3]);
    ul.z = pack_bf2(lo[4], lo[5]); ul.w = pack_bf2(lo[6], lo[7]);
    *reinterpret_cast<uint4*>(g_ahi + i) = uh;
    *reinterpret_cast<uint4*>(g_alo + i) = ul;
}

__global__ __launch_bounds__(256)
void conv_b_kernel(const float* __restrict__ Woff, const float* __restrict__ Wattn)
{
    const int n = blockIdx.x;    // 0..383 (output column = B^T row)
    const int k = threadIdx.x;   // 0..255
    float x = (n < 256) ? __ldg(Woff + (size_t)k * 256 + n)
                        : __ldg(Wattn + (size_t)k * 128 + (n - 256));
    __nv_bfloat16 h = __float2bfloat16(x);
    g_bhi[(size_t)n * EMBED + k] = h;
    g_blo[(size_t)n * EMBED + k] = __float2bfloat16(x - __bfloat162float(h));
}

// ======================= mma.sync GEMM kernel (unchanged from R7) =======================
#define LDA   72
#define A_HI  0
#define A_LO  18432
#define B_HI  36864
#define B_LO  55296
#define SMT   73728
#define LDD   132

__global__ __launch_bounds__(256)
void mma_gemm_kernel(const float* __restrict__ boff, const float* __restrict__ battn)
{
    extern __shared__ char smem[];
    const int tid  = threadIdx.x;
    const int wid  = tid >> 5;
    const int lane = tid & 31;
    const int bn   = blockIdx.y;
    const int rowg = blockIdx.x * 128;
    const uint32_t sb = smem_u32(smem);

    const int warp_m = (wid >> 1) * 32;
    const int warp_n = (wid & 1) * 64;

    float acc[2][8][4];
    #pragma unroll
    for (int mi = 0; mi < 2; mi++)
        #pragma unroll
        for (int nj = 0; nj < 8; nj++)
            #pragma unroll
            for (int c = 0; c < 4; c++) acc[mi][nj][c] = 0.f;

    for (int kc = 0; kc < 4; kc++) {
        const int k0 = kc * 64;
        __syncthreads();
        #pragma unroll
        for (int r = 0; r < 4; r++) {
            const int s = tid + r * 256;
            const int row = s >> 3, j = s & 7;
            const uint32_t doff = (uint32_t)(row * LDA + j * 8) * 2;
            const size_t asrc = (size_t)(rowg + row) * EMBED + k0 + j * 8;
            const size_t bsrc = (size_t)(bn * 128 + row) * EMBED + k0 + j * 8;
            *reinterpret_cast<uint4*>(smem + A_HI + doff) = *reinterpret_cast<const uint4*>(g_ahi + asrc);
            *reinterpret_cast<uint4*>(smem + A_LO + doff) = *reinterpret_cast<const uint4*>(g_alo + asrc);
            *reinterpret_cast<uint4*>(smem + B_HI + doff) = *reinterpret_cast<const uint4*>(g_bhi + bsrc);
            *reinterpret_cast<uint4*>(smem + B_LO + doff) = *reinterpret_cast<const uint4*>(g_blo + bsrc);
        }
        __syncthreads();

        #pragma unroll
        for (int ks = 0; ks < 4; ks++) {
            const int kk = ks * 16;

            uint32_t ah[2][4], al[2][4];
            const int ar = warp_m + (lane & 15);
            const int ac = kk + ((lane >> 4) << 3);
            #pragma unroll
            for (int mi = 0; mi < 2; mi++) {
                const uint32_t ad = sb + A_HI + (uint32_t)(((ar + mi * 16) * LDA + ac) << 1);
                ldsm4(ah[mi][0], ah[mi][1], ah[mi][2], ah[mi][3], ad);
                ldsm4(al[mi][0], al[mi][1], al[mi][2], al[mi][3], ad + (A_LO - A_HI));
            }

            uint32_t bhf[4][4], blf[4][4];
            const int br = warp_n + (lane & 7) + ((lane >> 4) << 3);
            const int bc = kk + (((lane >> 3) & 1) << 3);
            #pragma unroll
            for (int g = 0; g < 4; g++) {
                const uint32_t bd = sb + B_HI + (uint32_t)(((br + g * 16) * LDA + bc) << 1);
                ldsm4(bhf[g][0], bhf[g][1], bhf[g][2], bhf[g][3], bd);
                ldsm4(blf[g][0], blf[g][1], blf[g][2], blf[g][3], bd + (B_LO - B_HI));
            }

            #pragma unroll
            for (int mi = 0; mi < 2; mi++)
                #pragma unroll
                for (int nj = 0; nj < 8; nj++) {
                    const int g = nj >> 1, o = (nj & 1) * 2;
                    mma16816(acc[mi][nj], ah[mi], &bhf[g][o]);
                    mma16816(acc[mi][nj], ah[mi], &blf[g][o]);
                    mma16816(acc[mi][nj], al[mi], &bhf[g][o]);
                }
        }
    }

    __syncthreads();
    float* sD = reinterpret_cast<float*>(smem);
    #pragma unroll
    for (int mi = 0; mi < 2; mi++)
        #pragma unroll
        for (int nj = 0; nj < 8; nj++) {
            const int r0 = warp_m + mi * 16 + (lane >> 2);
            const int c0 = warp_n + nj * 8 + (lane & 3) * 2;
            *reinterpret_cast<float2*>(sD + r0 * LDD + c0)       = make_float2(acc[mi][nj][0], acc[mi][nj][1]);
            *reinterpret_cast<float2*>(sD + (r0 + 8) * LDD + c0) = make_float2(acc[mi][nj][2], acc[mi][nj][3]);
        }
    __syncthreads();

    const int row = tid >> 1;
    const int cp  = (tid & 1) * 64;
    float* orow = g_logits + (size_t)(rowg + row) * NLOGIT + bn * 128 + cp;

    #pragma unroll
    for (int g4 = 0; g4 < 4; g4++) {
        float f[16];
        #pragma unroll
        for (int j = 0; j < 16; j++) {
            const int c = cp + g4 * 16 + j;
            const float bias = (bn < 2) ? __ldg(boff + bn * 128 + c) : __ldg(battn + c);
            f[j] = sD[row * LDD + c] + bias;
        }
        if (bn == 2) {
            float mx = f[0];
            #pragma unroll
            for (int j = 1; j < 16; j++) mx = fmaxf(mx, f[j]);
            float s = 0.f;
            #pragma unroll
            for (int j = 0; j < 16; j++) { f[j] = __expf(f[j] - mx); s += f[j]; }
            const float rs = __fdividef(1.f, s);
            #pragma unroll
            for (int j = 0; j < 16; j++) f[j] *= rs;
        }
        #pragma unroll
        for (int j = 0; j < 16; j += 4)
            *reinterpret_cast<float4*>(orow + g4 * 16 + j) = make_float4(f[j], f[j+1], f[j+2], f[j+3]);
    }
}

// ======================= sampling kernel: 2 warps per (b,h,q) =======================
// Each (b,h,q) is handled by a warp PAIR: warp half=0 takes levels {0,1},
// half=1 takes levels {2,3}. Within a warp: psub = lane>>3 picks one of 4
// points of the level, dgrp = lane&7 covers the 32-dim head with float4 loads.
// Partial sums meet through 512B of smem. Halved per-warp serial chain,
// doubled warp count for latency hiding.
__global__ __launch_bounds__(256, 5)
void sample_kernel(const float* __restrict__ value,
                   const float* __restrict__ refp,
                   float* __restrict__ out)
{
    constexpr int cW[4]  = {100, 50, 25, 13};
    constexpr int cVS[4] = {0, 10000, 12500, 13125};

    __shared__ float4 part[4][8];

    const int wid  = threadIdx.x >> 5;
    const int lane = threadIdx.x & 31;
    const int gw   = blockIdx.x * 8 + wid;     // 0..255999
    const int slot = gw >> 1;                  // (b,h,q) index, 0..127999
    const int half = gw & 1;                   // 0: levels 0,1   1: levels 2,3

    const int q  = slot % LQ_;
    const int bh = slot / LQ_;
    const int b  = bh >> 3;
    const int h  = bh & 7;
    const int row = b * LQ_ + q;

    const float* lg = g_logits + (size_t)row * NLOGIT;
    const float4 rp = __ldg(reinterpret_cast<const float4*>(refp) + row);

    const int psub = lane >> 3;     // point within level
    const int dgrp = lane & 7;      // float4 within 32-dim head

    const float2* offp = reinterpret_cast<const float2*>(lg) + h * 16 + half * 8 + psub;
    const float*  app  = lg + 256 + h * 16 + half * 8 + psub;

    const float* vb = value + (size_t)b * LV_ * EMBED + h * HDIM + dgrp * 4;

    float4 acc = make_float4(0.f, 0.f, 0.f, 0.f);

    #pragma unroll
    for (int i2 = 0; i2 < 2; i2++) {
        const int it = half * 2 + i2;          // level index
        const int   W  = cW[it];
        const float Wf = (float)W;

        const float2 off = __ldg(offp + (i2 << 2));
        const float  ap  = __ldg(app  + (i2 << 2));

        const float px = fmaf(fmaf(off.x, 0.125f * rp.z, rp.x), Wf, -0.5f);
        const float py = fmaf(fmaf(off.y, 0.125f * rp.w, rp.y), Wf, -0.5f);
        const float fx0 = floorf(px), fy0 = floorf(py);
        const float fx = px - fx0,    fy = py - fy0;
        const int x0 = (int)fx0, y0 = (int)fy0;

        const float gx = 1.f - fx, gy = 1.f - fy;
        const float w00 = ap * gx * gy;
        const float w10 = ap * fx * gy;
        const float w01 = ap * gx * fy;
        const float w11 = ap * fx * fy;

        const bool xin0 = (unsigned)x0       < (unsigned)W;
        const bool xin1 = (unsigned)(x0 + 1) < (unsigned)W;
        const bool yin0 = (unsigned)y0       < (unsigned)W;   // H == W
        const bool yin1 = (unsigned)(y0 + 1) < (unsigned)W;

        const float* vl = vb + (ptrdiff_t)cVS[it] * EMBED
                             + (ptrdiff_t)(y0 * W + x0) * EMBED;

        float4 v00 = make_float4(0.f,0.f,0.f,0.f);
        float4 v10 = v00, v01 = v00, v11 = v00;
        if (xin0 && yin0) v00 = *reinterpret_cast<const float4*>(vl);
        if (xin1 && yin0) v10 = *reinterpret_cast<const float4*>(vl + EMBED);
        if (xin0 && yin1) v01 = *reinterpret_cast<const float4*>(vl + W * EMBED);
        if (xin1 && yin1) v11 = *reinterpret_cast<const float4*>(vl + W * EMBED + EMBED);

        acc.x = fmaf(w00, v00.x, fmaf(w10, v10.x, fmaf(w01, v01.x, fmaf(w11, v11.x, acc.x))));
        acc.y = fmaf(w00, v00.y, fmaf(w10, v10.y, fmaf(w01, v01.y, fmaf(w11, v11.y, acc.y))));
        acc.z = fmaf(w00, v00.z, fmaf(w10, v10.z, fmaf(w01, v01.z, fmaf(w11, v11.z, acc.z))));
        acc.w = fmaf(w00, v00.w, fmaf(w10, v10.w, fmaf(w01, v01.w, fmaf(w11, v11.w, acc.w))));
    }

    // reduce over the 4 point-slots of this warp
    #pragma unroll
    for (int o = 8; o <= 16; o <<= 1) {
        acc.x += __shfl_xor_sync(0xffffffffu, acc.x, o);
        acc.y += __shfl_xor_sync(0xffffffffu, acc.y, o);
        acc.z += __shfl_xor_sync(0xffffffffu, acc.z, o);
        acc.w += __shfl_xor_sync(0xffffffffu, acc.w, o);
    }

    // combine the two warps of the pair through smem
    const int sslot = wid >> 1;    // 0..3 (pair within block)
    if (half == 1 && psub == 0) part[sslot][dgrp] = acc;
    __syncthreads();
    if (half == 0 && psub == 0) {
        const float4 p2 = part[sslot][dgrp];
        acc.x += p2.x; acc.y += p2.y; acc.z += p2.z; acc.w += p2.w;
        *reinterpret_cast<float4*>(out + (size_t)row * EMBED + h * HDIM + dgrp * 4) = acc;
    }
}

// ---------------- launch ----------------
extern "C" void kernel_launch(void* const* d_in, const int* in_sizes, int n_in,
                              void* d_out, int out_size)
{
    (void)in_sizes; (void)n_in; (void)out_size;
    const float* query = (const float*)d_in[0];
    const float* refp  = (const float*)d_in[1];
    const float* value = (const float*)d_in[2];
    // d_in[3] = value_spatial_shapes (int64) — hardcoded
    const float* Woff  = (const float*)d_in[4];
    const float* boff  = (const float*)d_in[5];
    const float* Wattn = (const float*)d_in[6];
    const float* battn = (const float*)d_in[7];
    float* out = (float*)d_out;

    static bool attr_set = false;
    if (!attr_set) {
        cudaFuncSetAttribute(mma_gemm_kernel,
                             cudaFuncAttributeMaxDynamicSharedMemorySize, SMT);
        attr_set = true;
    }

    conv_a_kernel<<<(NROWS * EMBED / 8) / 256, 256>>>(query);
    conv_b_kernel<<<NLOGIT, 256>>>(Woff, Wattn);
    mma_gemm_kernel<<<dim3(NROWS / 128, 3), 256, SMT>>>(boff, battn);

    // 2 warps per (b,h,q): 256000 warps / 8 per block = 32000 blocks
    sample_kernel<<<(BS_ * NHEADS * LQ_ * 2) / 8, 256>>>(value, refp, out);
}

// round 10
// speedup vs baseline: 1.2233x; 1.2233x over previous
#include <cuda_runtime.h>
#include <cuda_bf16.h>
#include <cstdint>
#include <math.h>

// ---------------- problem constants ----------------
#define BS_      16
#define LQ_      1000
#define NROWS    (BS_*LQ_)         // 16000
#define EMBED    256
#define NHEADS   8
#define HDIM     32
#define NLOGIT   384               // 256 offset cols + 128 attn-prob cols
#define LV_      13294

__device__ float g_logits[NROWS * NLOGIT];      // off(256) | softmaxed attn(128)
__device__ __nv_bfloat16 g_bhi[NLOGIT * EMBED]; // B^T split-hi [n][k]
__device__ __nv_bfloat16 g_blo[NLOGIT * EMBED]; // B^T split-lo

// ======================= helpers =======================
__device__ __forceinline__ uint32_t smem_u32(const void* p) {
    uint32_t a;
    asm("{ .reg .u64 t; cvta.to.shared.u64 t, %1; cvt.u32.u64 %0, t; }" : "=r"(a) : "l"(p));
    return a;
}

__device__ __forceinline__ void ldsm4(uint32_t& r0, uint32_t& r1, uint32_t& r2, uint32_t& r3,
                                      uint32_t addr) {
    asm volatile("ldmatrix.sync.aligned.m8n8.x4.shared.b16 {%0,%1,%2,%3}, [%4];"
                 : "=r"(r0), "=r"(r1), "=r"(r2), "=r"(r3) : "r"(addr));
}

__device__ __forceinline__ void mma16816(float* c, const uint32_t* a, const uint32_t* b) {
    asm volatile(
        "mma.sync.aligned.m16n8k16.row.col.f32.bf16.bf16.f32 "
        "{%0,%1,%2,%3}, {%4,%5,%6,%7}, {%8,%9}, {%0,%1,%2,%3};"
        : "+f"(c[0]), "+f"(c[1]), "+f"(c[2]), "+f"(c[3])
        : "r"(a[0]), "r"(a[1]), "r"(a[2]), "r"(a[3]), "r"(b[0]), "r"(b[1]));
}

__device__ __forceinline__ uint32_t pack_bf2(__nv_bfloat16 a, __nv_bfloat16 b) {
    return (uint32_t)__bfloat16_as_ushort(a) | ((uint32_t)__bfloat16_as_ushort(b) << 16);
}

// ======================= B conversion kernel (transpose + hi/lo split) =======================
__global__ __launch_bounds__(256)
void conv_b_kernel(const float* __restrict__ Woff, const float* __restrict__ Wattn)
{
    const int n = blockIdx.x;    // 0..383 (output column = B^T row)
    const int k = threadIdx.x;   // 0..255
    float x = (n < 256) ? __ldg(Woff + (size_t)k * 256 + n)
                        : __ldg(Wattn + (size_t)k * 128 + (n - 256));
    __nv_bfloat16 h = __float2bfloat16(x);
    g_bhi[(size_t)n * EMBED + k] = h;
    g_blo[(size_t)n * EMBED + k] = __float2bfloat16(x - __bfloat162float(h));
}

// ======================= mma.sync GEMM kernel (fused A hi/lo split) =======================
// C[16000,384] = Q @ [W_off|W_attn]^T via split-bf16 (Ah*Bh + Ah*Bl + Al*Bh), fp32 acc.
// A's hi/lo decomposition happens in the staging loop (fp32 Q -> bf16x2 in-register),
// eliminating the separate conv_a kernel and its 33 MB of scratch traffic.
#define LDA   72
#define A_HI  0
#define A_LO  18432
#define B_HI  36864
#define B_LO  55296
#define SMT   73728
#define LDD   132

__global__ __launch_bounds__(256)
void mma_gemm_kernel(const float* __restrict__ Q,
                     const float* __restrict__ boff, const float* __restrict__ battn)
{
    extern __shared__ char smem[];
    const int tid  = threadIdx.x;
    const int wid  = tid >> 5;
    const int lane = tid & 31;
    const int bn   = blockIdx.y;
    const int rowg = blockIdx.x * 128;
    const uint32_t sb = smem_u32(smem);

    const int warp_m = (wid >> 1) * 32;
    const int warp_n = (wid & 1) * 64;

    float acc[2][8][4];
    #pragma unroll
    for (int mi = 0; mi < 2; mi++)
        #pragma unroll
        for (int nj = 0; nj < 8; nj++)
            #pragma unroll
            for (int c = 0; c < 4; c++) acc[mi][nj][c] = 0.f;

    for (int kc = 0; kc < 4; kc++) {
        const int k0 = kc * 64;
        __syncthreads();
        #pragma unroll
        for (int r = 0; r < 4; r++) {
            const int s = tid + r * 256;
            const int row = s >> 3, j = s & 7;
            const uint32_t doff = (uint32_t)(row * LDA + j * 8) * 2;

            // --- A: load fp32, split to bf16 hi/lo in-register ---
            const float* asrc = Q + (size_t)(rowg + row) * EMBED + k0 + j * 8;
            const float4 a0 = __ldg(reinterpret_cast<const float4*>(asrc));
            const float4 a1 = __ldg(reinterpret_cast<const float4*>(asrc) + 1);
            const float av[8] = {a0.x, a0.y, a0.z, a0.w, a1.x, a1.y, a1.z, a1.w};
            __nv_bfloat16 hi[8], lo[8];
            #pragma unroll
            for (int t = 0; t < 8; t++) {
                hi[t] = __float2bfloat16(av[t]);
                lo[t] = __float2bfloat16(av[t] - __bfloat162float(hi[t]));
            }
            uint4 uh, ul;
            uh.x = pack_bf2(hi[0], hi[1]); uh.y = pack_bf2(hi[2], hi[3]);
            uh.z = pack_bf2(hi[4], hi[5]); uh.w = pack_bf2(hi[6], hi[7]);
            ul.x = pack_bf2(lo[0], lo[1]); ul.y = pack_bf2(lo[2], lo[3]);
            ul.z = pack_bf2(lo[4], lo[5]); ul.w = pack_bf2(lo[6], lo[7]);
            *reinterpret_cast<uint4*>(smem + A_HI + doff) = uh;
            *reinterpret_cast<uint4*>(smem + A_LO + doff) = ul;

            // --- B: pre-split bf16 from conv_b ---
            const size_t bsrc = (size_t)(bn * 128 + row) * EMBED + k0 + j * 8;
            *reinterpret_cast<uint4*>(smem + B_HI + doff) = *reinterpret_cast<const uint4*>(g_bhi + bsrc);
            *reinterpret_cast<uint4*>(smem + B_LO + doff) = *reinterpret_cast<const uint4*>(g_blo + bsrc);
        }
        __syncthreads();

        #pragma unroll
        for (int ks = 0; ks < 4; ks++) {
            const int kk = ks * 16;

            uint32_t ah[2][4], al[2][4];
            const int ar = warp_m + (lane & 15);
            const int ac = kk + ((lane >> 4) << 3);
            #pragma unroll
            for (int mi = 0; mi < 2; mi++) {
                const uint32_t ad = sb + A_HI + (uint32_t)(((ar + mi * 16) * LDA + ac) << 1);
                ldsm4(ah[mi][0], ah[mi][1], ah[mi][2], ah[mi][3], ad);
                ldsm4(al[mi][0], al[mi][1], al[mi][2], al[mi][3], ad + (A_LO - A_HI));
            }

            uint32_t bhf[4][4], blf[4][4];
            const int br = warp_n + (lane & 7) + ((lane >> 4) << 3);
            const int bc = kk + (((lane >> 3) & 1) << 3);
            #pragma unroll
            for (int g = 0; g < 4; g++) {
                const uint32_t bd = sb + B_HI + (uint32_t)(((br + g * 16) * LDA + bc) << 1);
                ldsm4(bhf[g][0], bhf[g][1], bhf[g][2], bhf[g][3], bd);
                ldsm4(blf[g][0], blf[g][1], blf[g][2], blf[g][3], bd + (B_LO - B_HI));
            }

            #pragma unroll
            for (int mi = 0; mi < 2; mi++)
                #pragma unroll
                for (int nj = 0; nj < 8; nj++) {
                    const int g = nj >> 1, o = (nj & 1) * 2;
                    mma16816(acc[mi][nj], ah[mi], &bhf[g][o]);
                    mma16816(acc[mi][nj], ah[mi], &blf[g][o]);
                    mma16816(acc[mi][nj], al[mi], &bhf[g][o]);
                }
        }
    }

    __syncthreads();
    float* sD = reinterpret_cast<float*>(smem);
    #pragma unroll
    for (int mi = 0; mi < 2; mi++)
        #pragma unroll
        for (int nj = 0; nj < 8; nj++) {
            const int r0 = warp_m + mi * 16 + (lane >> 2);
            const int c0 = warp_n + nj * 8 + (lane & 3) * 2;
            *reinterpret_cast<float2*>(sD + r0 * LDD + c0)       = make_float2(acc[mi][nj][0], acc[mi][nj][1]);
            *reinterpret_cast<float2*>(sD + (r0 + 8) * LDD + c0) = make_float2(acc[mi][nj][2], acc[mi][nj][3]);
        }
    __syncthreads();

    const int row = tid >> 1;
    const int cp  = (tid & 1) * 64;
    float* orow = g_logits + (size_t)(rowg + row) * NLOGIT + bn * 128 + cp;

    #pragma unroll
    for (int g4 = 0; g4 < 4; g4++) {
        float f[16];
        #pragma unroll
        for (int j = 0; j < 16; j++) {
            const int c = cp + g4 * 16 + j;
            const float bias = (bn < 2) ? __ldg(boff + bn * 128 + c) : __ldg(battn + c);
            f[j] = sD[row * LDD + c] + bias;
        }
        if (bn == 2) {
            float mx = f[0];
            #pragma unroll
            for (int j = 1; j < 16; j++) mx = fmaxf(mx, f[j]);
            float s = 0.f;
            #pragma unroll
            for (int j = 0; j < 16; j++) { f[j] = __expf(f[j] - mx); s += f[j]; }
            const float rs = __fdividef(1.f, s);
            #pragma unroll
            for (int j = 0; j < 16; j++) f[j] *= rs;
        }
        #pragma unroll
        for (int j = 0; j < 16; j += 4)
            *reinterpret_cast<float4*>(orow + g4 * 16 + j) = make_float4(f[j], f[j+1], f[j+2], f[j+3]);
    }
}

// ======================= sampling kernel (R7 configuration — local optimum) =======================
// one warp per (b, h, q): psub = lane>>3 picks one of 4 parallel points of a
// level, dgrp = lane&7 covers the 32-dim head with float4 loads; per-lane
// coordinate recompute from broadcast lines, shuffles only in the final reduce.
__global__ __launch_bounds__(256, 6)
void sample_kernel(const float* __restrict__ value,
                   const float* __restrict__ refp,
                   float* __restrict__ out)
{
    constexpr int cW[4]  = {100, 50, 25, 13};
    constexpr int cVS[4] = {0, 10000, 12500, 13125};

    const int warp = (blockIdx.x << 3) + (threadIdx.x >> 5);
    const int lane = threadIdx.x & 31;

    const int q  = warp % LQ_;
    const int bh = warp / LQ_;
    const int b  = bh >> 3;
    const int h  = bh & 7;
    const int row = b * LQ_ + q;

    const float* lg = g_logits + (size_t)row * NLOGIT;
    const float4 rp = __ldg(reinterpret_cast<const float4*>(refp) + row);

    const int psub = lane >> 3;
    const int dgrp = lane & 7;

    const float2* offp = reinterpret_cast<const float2*>(lg) + h * 16 + psub;
    const float*  app  = lg + 256 + h * 16 + psub;

    float2 off[4];
    float  ap[4];
    #pragma unroll
    for (int it = 0; it < 4; it++) {
        off[it] = __ldg(offp + (it << 2));
        ap[it]  = __ldg(app  + (it << 2));
    }

    const float* vb = value + (size_t)b * LV_ * EMBED + h * HDIM + dgrp * 4;

    float4 acc0 = make_float4(0.f, 0.f, 0.f, 0.f);
    float4 acc1 = acc0;

    #pragma unroll
    for (int it = 0; it < 4; it++) {
        const int   W  = cW[it];
        const float Wf = (float)W;

        const float px = fmaf(fmaf(off[it].x, 0.125f * rp.z, rp.x), Wf, -0.5f);
        const float py = fmaf(fmaf(off[it].y, 0.125f * rp.w, rp.y), Wf, -0.5f);
        const float fx0 = floorf(px), fy0 = floorf(py);
        const float fx = px - fx0,    fy = py - fy0;
        const int x0 = (int)fx0, y0 = (int)fy0;

        const float gx = 1.f - fx, gy = 1.f - fy;
        const float w00 = ap[it] * gx * gy;
        const float w10 = ap[it] * fx * gy;
        const float w01 = ap[it] * gx * fy;
        const float w11 = ap[it] * fx * fy;

        const bool xin0 = (unsigned)x0       < (unsigned)W;
        const bool xin1 = (unsigned)(x0 + 1) < (unsigned)W;
        const bool yin0 = (unsigned)y0       < (unsigned)W;   // H == W
        const bool yin1 = (unsigned)(y0 + 1) < (unsigned)W;

        const float* vl = vb + (ptrdiff_t)cVS[it] * EMBED
                             + (ptrdiff_t)(y0 * W + x0) * EMBED;

        float4 v00 = make_float4(0.f,0.f,0.f,0.f);
        float4 v10 = v00, v01 = v00, v11 = v00;
        if (xin0 && yin0) v00 = *reinterpret_cast<const float4*>(vl);
        if (xin1 && yin0) v10 = *reinterpret_cast<const float4*>(vl + EMBED);
        if (xin0 && yin1) v01 = *reinterpret_cast<const float4*>(vl + W * EMBED);
        if (xin1 && yin1) v11 = *reinterpret_cast<const float4*>(vl + W * EMBED + EMBED);

        float4& acc = (it & 1) ? acc1 : acc0;
        acc.x = fmaf(w00, v00.x, fmaf(w10, v10.x, fmaf(w01, v01.x, fmaf(w11, v11.x, acc.x))));
        acc.y = fmaf(w00, v00.y, fmaf(w10, v10.y, fmaf(w01, v01.y, fmaf(w11, v11.y, acc.y))));
        acc.z = fmaf(w00, v00.z, fmaf(w10, v10.z, fmaf(w01, v01.z, fmaf(w11, v11.z, acc.z))));
        acc.w = fmaf(w00, v00.w, fmaf(w10, v10.w, fmaf(w01, v01.w, fmaf(w11, v11.w, acc.w))));
    }

    float4 acc;
    acc.x = acc0.x + acc1.x;
    acc.y = acc0.y + acc1.y;
    acc.z = acc0.z + acc1.z;
    acc.w = acc0.w + acc1.w;

    #pragma unroll
    for (int o = 8; o <= 16; o <<= 1) {
        acc.x += __shfl_xor_sync(0xffffffffu, acc.x, o);
        acc.y += __shfl_xor_sync(0xffffffffu, acc.y, o);
        acc.z += __shfl_xor_sync(0xffffffffu, acc.z, o);
        acc.w += __shfl_xor_sync(0xffffffffu, acc.w, o);
    }

    if (psub == 0) {
        *reinterpret_cast<float4*>(out + (size_t)row * EMBED + h * HDIM + dgrp * 4) = acc;
    }
}

// ---------------- launch ----------------
extern "C" void kernel_launch(void* const* d_in, const int* in_sizes, int n_in,
                              void* d_out, int out_size)
{
    (void)in_sizes; (void)n_in; (void)out_size;
    const float* query = (const float*)d_in[0];
    const float* refp  = (const float*)d_in[1];
    const float* value = (const float*)d_in[2];
    // d_in[3] = value_spatial_shapes (int64) — hardcoded
    const float* Woff  = (const float*)d_in[4];
    const float* boff  = (const float*)d_in[5];
    const float* Wattn = (const float*)d_in[6];
    const float* battn = (const float*)d_in[7];
    float* out = (float*)d_out;

    static bool attr_set = false;
    if (!attr_set) {
        cudaFuncSetAttribute(mma_gemm_kernel,
                             cudaFuncAttributeMaxDynamicSharedMemorySize, SMT);
        attr_set = true;
    }

    conv_b_kernel<<<NLOGIT, 256>>>(Woff, Wattn);
    mma_gemm_kernel<<<dim3(NROWS / 128, 3), 256, SMT>>>(query, boff, battn);
    sample_kernel<<<(BS_ * NHEADS * LQ_) / 8, 256>>>(value, refp, out);
}

// round 11
// speedup vs baseline: 1.2842x; 1.0498x over previous
#include <cuda_runtime.h>
#include <cuda_bf16.h>
#include <cstdint>
#include <math.h>

// ---------------- problem constants ----------------
#define BS_      16
#define LQ_      1000
#define NROWS    (BS_*LQ_)         // 16000
#define EMBED    256
#define NHEADS   8
#define HDIM     32
#define NLOGIT   384               // 256 offset cols + 128 attn-prob cols
#define LV_      13294

__device__ float g_logits[NROWS * NLOGIT];      // off(256) | softmaxed attn(128)
__device__ __nv_bfloat16 g_bhi[NLOGIT * EMBED]; // B^T split-hi [n][k]
__device__ __nv_bfloat16 g_blo[NLOGIT * EMBED]; // B^T split-lo

// ======================= helpers =======================
__device__ __forceinline__ uint32_t smem_u32(const void* p) {
    uint32_t a;
    asm("{ .reg .u64 t; cvta.to.shared.u64 t, %1; cvt.u32.u64 %0, t; }" : "=r"(a) : "l"(p));
    return a;
}

__device__ __forceinline__ void ldsm4(uint32_t& r0, uint32_t& r1, uint32_t& r2, uint32_t& r3,
                                      uint32_t addr) {
    asm volatile("ldmatrix.sync.aligned.m8n8.x4.shared.b16 {%0,%1,%2,%3}, [%4];"
                 : "=r"(r0), "=r"(r1), "=r"(r2), "=r"(r3) : "r"(addr));
}

__device__ __forceinline__ void mma16816(float* c, const uint32_t* a, const uint32_t* b) {
    asm volatile(
        "mma.sync.aligned.m16n8k16.row.col.f32.bf16.bf16.f32 "
        "{%0,%1,%2,%3}, {%4,%5,%6,%7}, {%8,%9}, {%0,%1,%2,%3};"
        : "+f"(c[0]), "+f"(c[1]), "+f"(c[2]), "+f"(c[3])
        : "r"(a[0]), "r"(a[1]), "r"(a[2]), "r"(a[3]), "r"(b[0]), "r"(b[1]));
}

__device__ __forceinline__ uint32_t pack_bf2(__nv_bfloat16 a, __nv_bfloat16 b) {
    return (uint32_t)__bfloat16_as_ushort(a) | ((uint32_t)__bfloat16_as_ushort(b) << 16);
}

// ======================= B conversion (coalesced smem transpose) =======================
// 12 blocks, each handles a 32-column n-tile x all 256 k.
// Phase 1: coalesced fp32 reads over n, hi/lo split, staged transposed in smem.
// Phase 2: vectorized uint4 writes over k.
#define CB_PAD 260
__global__ __launch_bounds__(256)
void conv_b_kernel(const float* __restrict__ Woff, const float* __restrict__ Wattn)
{
    __shared__ __nv_bfloat16 sHI[32][CB_PAD];
    __shared__ __nv_bfloat16 sLO[32][CB_PAD];

    const int blk = blockIdx.x;             // 0..11
    const int nx  = threadIdx.x & 31;
    const int ky  = threadIdx.x >> 5;       // 0..7
    const int n   = blk * 32 + nx;
    const bool attn = (n >= 256);
    const float* src  = attn ? (Wattn + (n - 256)) : (Woff + n);
    const int    lds_ = attn ? 128 : 256;

    #pragma unroll
    for (int k0 = 0; k0 < 256; k0 += 8) {
        const int k = k0 + ky;
        const float x = __ldg(src + (size_t)k * lds_);
        const __nv_bfloat16 h = __float2bfloat16(x);
        sHI[nx][k] = h;
        sLO[nx][k] = __float2bfloat16(x - __bfloat162float(h));
    }
    __syncthreads();

    const int n2 = threadIdx.x >> 3;        // 0..31
    const int jg = threadIdx.x & 7;         // 0..7
    const int gn = blk * 32 + n2;
    #pragma unroll
    for (int v = 0; v < 4; v++) {
        const int k = jg * 32 + v * 8;
        const __nv_bfloat16* ph = &sHI[n2][k];
        const __nv_bfloat16* pl = &sLO[n2][k];
        uint4 uh, ul;
        uh.x = pack_bf2(ph[0], ph[1]); uh.y = pack_bf2(ph[2], ph[3]);
        uh.z = pack_bf2(ph[4], ph[5]); uh.w = pack_bf2(ph[6], ph[7]);
        ul.x = pack_bf2(pl[0], pl[1]); ul.y = pack_bf2(pl[2], pl[3]);
        ul.z = pack_bf2(pl[4], pl[5]); ul.w = pack_bf2(pl[6], pl[7]);
        *reinterpret_cast<uint4*>(g_bhi + (size_t)gn * EMBED + k) = uh;
        *reinterpret_cast<uint4*>(g_blo + (size_t)gn * EMBED + k) = ul;
    }
}

// ======================= mma.sync GEMM kernel (M=64 tiles) =======================
// C[16000,384] = Q @ [W_off|W_attn]^T via split-bf16 (Ah*Bh + Ah*Bl + Al*Bh), fp32 acc.
// grid (250, 3): CTA tile 64(M) x 128(N), K = 256 chunked 4 x 64. 8 warps,
// warp tile 16(M) x 64(N). A hi/lo split fused into staging. Smaller CTAs cut
// wave-quantization loss (375 CTAs @2/SM = 63% util -> 750 CTAs = 84%).
#define LDA   72
#define A_HI  0
#define A_LO  9216                 // 64*72*2
#define B_HI  18432
#define B_LO  36864                // +128*72*2
#define SMT   55296
#define LDD   132

__global__ __launch_bounds__(256)
void mma_gemm_kernel(const float* __restrict__ Q,
                     const float* __restrict__ boff, const float* __restrict__ battn)
{
    extern __shared__ char smem[];
    const int tid  = threadIdx.x;
    const int wid  = tid >> 5;
    const int lane = tid & 31;
    const int bn   = blockIdx.y;
    const int rowg = blockIdx.x * 64;
    const uint32_t sb = smem_u32(smem);

    const int warp_m = (wid >> 1) * 16;     // 0,16,32,48
    const int warp_n = (wid & 1) * 64;      // 0,64

    float acc[8][4];
    #pragma unroll
    for (int nj = 0; nj < 8; nj++)
        #pragma unroll
        for (int c = 0; c < 4; c++) acc[nj][c] = 0.f;

    for (int kc = 0; kc < 4; kc++) {
        const int k0 = kc * 64;
        __syncthreads();

        // --- A: 64 rows x 64 k, fp32 -> bf16 hi/lo in-register ---
        #pragma unroll
        for (int r = 0; r < 2; r++) {
            const int s = tid + r * 256;        // 0..511
            const int row = s >> 3, j = s & 7;
            const uint32_t doff = (uint32_t)(row * LDA + j * 8) * 2;
            const float* asrc = Q + (size_t)(rowg + row) * EMBED + k0 + j * 8;
            const float4 a0 = __ldg(reinterpret_cast<const float4*>(asrc));
            const float4 a1 = __ldg(reinterpret_cast<const float4*>(asrc) + 1);
            const float av[8] = {a0.x, a0.y, a0.z, a0.w, a1.x, a1.y, a1.z, a1.w};
            __nv_bfloat16 hi[8], lo[8];
            #pragma unroll
            for (int t = 0; t < 8; t++) {
                hi[t] = __float2bfloat16(av[t]);
                lo[t] = __float2bfloat16(av[t] - __bfloat162float(hi[t]));
            }
            uint4 uh, ul;
            uh.x = pack_bf2(hi[0], hi[1]); uh.y = pack_bf2(hi[2], hi[3]);
            uh.z = pack_bf2(hi[4], hi[5]); uh.w = pack_bf2(hi[6], hi[7]);
            ul.x = pack_bf2(lo[0], lo[1]); ul.y = pack_bf2(lo[2], lo[3]);
            ul.z = pack_bf2(lo[4], lo[5]); ul.w = pack_bf2(lo[6], lo[7]);
            *reinterpret_cast<uint4*>(smem + A_HI + doff) = uh;
            *reinterpret_cast<uint4*>(smem + A_LO + doff) = ul;
        }
        // --- B: 128 n-rows x 64 k, pre-split bf16 ---
        #pragma unroll
        for (int r = 0; r < 4; r++) {
            const int s = tid + r * 256;        // 0..1023
            const int row = s >> 3, j = s & 7;
            const uint32_t doff = (uint32_t)(row * LDA + j * 8) * 2;
            const size_t bsrc = (size_t)(bn * 128 + row) * EMBED + k0 + j * 8;
            *reinterpret_cast<uint4*>(smem + B_HI + doff) = *reinterpret_cast<const uint4*>(g_bhi + bsrc);
            *reinterpret_cast<uint4*>(smem + B_LO + doff) = *reinterpret_cast<const uint4*>(g_blo + bsrc);
        }
        __syncthreads();

        #pragma unroll
        for (int ks = 0; ks < 4; ks++) {
            const int kk = ks * 16;

            uint32_t ah[4], al[4];
            const int ar = warp_m + (lane & 15);
            const int ac = kk + ((lane >> 4) << 3);
            const uint32_t ad = sb + A_HI + (uint32_t)((ar * LDA + ac) << 1);
            ldsm4(ah[0], ah[1], ah[2], ah[3], ad);
            ldsm4(al[0], al[1], al[2], al[3], ad + (A_LO - A_HI));

            uint32_t bhf[4][4], blf[4][4];
            const int br = warp_n + (lane & 7) + ((lane >> 4) << 3);
            const int bc = kk + (((lane >> 3) & 1) << 3);
            #pragma unroll
            for (int g = 0; g < 4; g++) {
                const uint32_t bd = sb + B_HI + (uint32_t)(((br + g * 16) * LDA + bc) << 1);
                ldsm4(bhf[g][0], bhf[g][1], bhf[g][2], bhf[g][3], bd);
                ldsm4(blf[g][0], blf[g][1], blf[g][2], blf[g][3], bd + (B_LO - B_HI));
            }

            #pragma unroll
            for (int nj = 0; nj < 8; nj++) {
                const int g = nj >> 1, o = (nj & 1) * 2;
                mma16816(acc[nj], ah, &bhf[g][o]);
                mma16816(acc[nj], ah, &blf[g][o]);
                mma16816(acc[nj], al, &bhf[g][o]);
            }
        }
    }

    // ---- accumulators -> reused smem D tile [64][LDD] ----
    __syncthreads();
    float* sD = reinterpret_cast<float*>(smem);
    #pragma unroll
    for (int nj = 0; nj < 8; nj++) {
        const int r0 = warp_m + (lane >> 2);
        const int c0 = warp_n + nj * 8 + (lane & 3) * 2;
        *reinterpret_cast<float2*>(sD + r0 * LDD + c0)       = make_float2(acc[nj][0], acc[nj][1]);
        *reinterpret_cast<float2*>(sD + (r0 + 8) * LDD + c0) = make_float2(acc[nj][2], acc[nj][3]);
    }
    __syncthreads();

    // ---- epilogue: bias (+softmax for attn block) -> g_logits ----
    const int row = tid >> 2;              // 0..63
    const int cs  = (tid & 3) * 32;        // 0,32,64,96
    float* orow = g_logits + (size_t)(rowg + row) * NLOGIT + bn * 128 + cs;

    float f[32];
    #pragma unroll
    for (int j = 0; j < 32; j++) {
        const int c = cs + j;
        const float bias = (bn < 2) ? __ldg(boff + bn * 128 + c) : __ldg(battn + c);
        f[j] = sD[row * LDD + c] + bias;
    }
    if (bn == 2) {
        #pragma unroll
        for (int g = 0; g < 2; g++) {
            float mx = f[g * 16];
            #pragma unroll
            for (int j = 1; j < 16; j++) mx = fmaxf(mx, f[g * 16 + j]);
            float s = 0.f;
            #pragma unroll
            for (int j = 0; j < 16; j++) { f[g * 16 + j] = __expf(f[g * 16 + j] - mx); s += f[g * 16 + j]; }
            const float rs = __fdividef(1.f, s);
            #pragma unroll
            for (int j = 0; j < 16; j++) f[g * 16 + j] *= rs;
        }
    }
    #pragma unroll
    for (int j = 0; j < 32; j += 4)
        *reinterpret_cast<float4*>(orow + j) = make_float4(f[j], f[j+1], f[j+2], f[j+3]);
}

// ======================= sampling kernel (R7 configuration — local optimum) =======================
__global__ __launch_bounds__(256, 6)
void sample_kernel(const float* __restrict__ value,
                   const float* __restrict__ refp,
                   float* __restrict__ out)
{
    constexpr int cW[4]  = {100, 50, 25, 13};
    constexpr int cVS[4] = {0, 10000, 12500, 13125};

    const int warp = (blockIdx.x << 3) + (threadIdx.x >> 5);
    const int lane = threadIdx.x & 31;

    const int q  = warp % LQ_;
    const int bh = warp / LQ_;
    const int b  = bh >> 3;
    const int h  = bh & 7;
    const int row = b * LQ_ + q;

    const float* lg = g_logits + (size_t)row * NLOGIT;
    const float4 rp = __ldg(reinterpret_cast<const float4*>(refp) + row);

    const int psub = lane >> 3;
    const int dgrp = lane & 7;

    const float2* offp = reinterpret_cast<const float2*>(lg) + h * 16 + psub;
    const float*  app  = lg + 256 + h * 16 + psub;

    float2 off[4];
    float  ap[4];
    #pragma unroll
    for (int it = 0; it < 4; it++) {
        off[it] = __ldg(offp + (it << 2));
        ap[it]  = __ldg(app  + (it << 2));
    }

    const float* vb = value + (size_t)b * LV_ * EMBED + h * HDIM + dgrp * 4;

    float4 acc0 = make_float4(0.f, 0.f, 0.f, 0.f);
    float4 acc1 = acc0;

    #pragma unroll
    for (int it = 0; it < 4; it++) {
        const int   W  = cW[it];
        const float Wf = (float)W;

        const float px = fmaf(fmaf(off[it].x, 0.125f * rp.z, rp.x), Wf, -0.5f);
        const float py = fmaf(fmaf(off[it].y, 0.125f * rp.w, rp.y), Wf, -0.5f);
        const float fx0 = floorf(px), fy0 = floorf(py);
        const float fx = px - fx0,    fy = py - fy0;
        const int x0 = (int)fx0, y0 = (int)fy0;

        const float gx = 1.f - fx, gy = 1.f - fy;
        const float w00 = ap[it] * gx * gy;
        const float w10 = ap[it] * fx * gy;
        const float w01 = ap[it] * gx * fy;
        const float w11 = ap[it] * fx * fy;

        const bool xin0 = (unsigned)x0       < (unsigned)W;
        const bool xin1 = (unsigned)(x0 + 1) < (unsigned)W;
        const bool yin0 = (unsigned)y0       < (unsigned)W;   // H == W
        const bool yin1 = (unsigned)(y0 + 1) < (unsigned)W;

        const float* vl = vb + (ptrdiff_t)cVS[it] * EMBED
                             + (ptrdiff_t)(y0 * W + x0) * EMBED;

        float4 v00 = make_float4(0.f,0.f,0.f,0.f);
        float4 v10 = v00, v01 = v00, v11 = v00;
        if (xin0 && yin0) v00 = *reinterpret_cast<const float4*>(vl);
        if (xin1 && yin0) v10 = *reinterpret_cast<const float4*>(vl + EMBED);
        if (xin0 && yin1) v01 = *reinterpret_cast<const float4*>(vl + W * EMBED);
        if (xin1 && yin1) v11 = *reinterpret_cast<const float4*>(vl + W * EMBED + EMBED);

        float4& acc = (it & 1) ? acc1 : acc0;
        acc.x = fmaf(w00, v00.x, fmaf(w10, v10.x, fmaf(w01, v01.x, fmaf(w11, v11.x, acc.x))));
        acc.y = fmaf(w00, v00.y, fmaf(w10, v10.y, fmaf(w01, v01.y, fmaf(w11, v11.y, acc.y))));
        acc.z = fmaf(w00, v00.z, fmaf(w10, v10.z, fmaf(w01, v01.z, fmaf(w11, v11.z, acc.z))));
        acc.w = fmaf(w00, v00.w, fmaf(w10, v10.w, fmaf(w01, v01.w, fmaf(w11, v11.w, acc.w))));
    }

    float4 acc;
    acc.x = acc0.x + acc1.x;
    acc.y = acc0.y + acc1.y;
    acc.z = acc0.z + acc1.z;
    acc.w = acc0.w + acc1.w;

    #pragma unroll
    for (int o = 8; o <= 16; o <<= 1) {
        acc.x += __shfl_xor_sync(0xffffffffu, acc.x, o);
        acc.y += __shfl_xor_sync(0xffffffffu, acc.y, o);
        acc.z += __shfl_xor_sync(0xffffffffu, acc.z, o);
        acc.w += __shfl_xor_sync(0xffffffffu, acc.w, o);
    }

    if (psub == 0) {
        *reinterpret_cast<float4*>(out + (size_t)row * EMBED + h * HDIM + dgrp * 4) = acc;
    }
}

// ---------------- launch ----------------
extern "C" void kernel_launch(void* const* d_in, const int* in_sizes, int n_in,
                              void* d_out, int out_size)
{
    (void)in_sizes; (void)n_in; (void)out_size;
    const float* query = (const float*)d_in[0];
    const float* refp  = (const float*)d_in[1];
    const float* value = (const float*)d_in[2];
    // d_in[3] = value_spatial_shapes (int64) — hardcoded
    const float* Woff  = (const float*)d_in[4];
    const float* boff  = (const float*)d_in[5];
    const float* Wattn = (const float*)d_in[6];
    const float* battn = (const float*)d_in[7];
    float* out = (float*)d_out;

    static bool attr_set = false;
    if (!attr_set) {
        cudaFuncSetAttribute(mma_gemm_kernel,
                             cudaFuncAttributeMaxDynamicSharedMemorySize, SMT);
        attr_set = true;
    }

    conv_b_kernel<<<NLOGIT / 32, 256>>>(Woff, Wattn);
    mma_gemm_kernel<<<dim3(NROWS / 64, 3), 256, SMT>>>(query, boff, battn);
    sample_kernel<<<(BS_ * NHEADS * LQ_) / 8, 256>>>(value, refp, out);
}

// round 12
// speedup vs baseline: 1.3004x; 1.0126x over previous
#include <cuda_runtime.h>
#include <cuda_bf16.h>
#include <cstdint>
#include <math.h>

// ---------------- problem constants ----------------
#define BS_      16
#define LQ_      1000
#define NROWS    (BS_*LQ_)         // 16000
#define EMBED    256
#define NHEADS   8
#define HDIM     32
#define NLOGIT   384               // 256 offset cols + 128 attn-prob cols
#define LV_      13294

__device__ float g_logits[NROWS * NLOGIT];      // off(256) | softmaxed attn(128)
__device__ __nv_bfloat16 g_bhi[NLOGIT * EMBED]; // B^T split-hi [n][k]
__device__ __nv_bfloat16 g_blo[NLOGIT * EMBED]; // B^T split-lo

// ======================= helpers =======================
__device__ __forceinline__ uint32_t smem_u32(const void* p) {
    uint32_t a;
    asm("{ .reg .u64 t; cvta.to.shared.u64 t, %1; cvt.u32.u64 %0, t; }" : "=r"(a) : "l"(p));
    return a;
}

__device__ __forceinline__ void ldsm4(uint32_t& r0, uint32_t& r1, uint32_t& r2, uint32_t& r3,
                                      uint32_t addr) {
    asm volatile("ldmatrix.sync.aligned.m8n8.x4.shared.b16 {%0,%1,%2,%3}, [%4];"
                 : "=r"(r0), "=r"(r1), "=r"(r2), "=r"(r3) : "r"(addr));
}

__device__ __forceinline__ void mma16816(float* c, const uint32_t* a, const uint32_t* b) {
    asm volatile(
        "mma.sync.aligned.m16n8k16.row.col.f32.bf16.bf16.f32 "
        "{%0,%1,%2,%3}, {%4,%5,%6,%7}, {%8,%9}, {%0,%1,%2,%3};"
        : "+f"(c[0]), "+f"(c[1]), "+f"(c[2]), "+f"(c[3])
        : "r"(a[0]), "r"(a[1]), "r"(a[2]), "r"(a[3]), "r"(b[0]), "r"(b[1]));
}

__device__ __forceinline__ uint32_t pack_bf2(__nv_bfloat16 a, __nv_bfloat16 b) {
    return (uint32_t)__bfloat16_as_ushort(a) | ((uint32_t)__bfloat16_as_ushort(b) << 16);
}

#define CP_ASYNC16(dst, src) \
    asm volatile("cp.async.cg.shared.global [%0], [%1], 16;" :: "r"(dst), "l"(src))
#define CP_COMMIT() asm volatile("cp.async.commit_group;" ::: "memory")
#define CP_WAIT1()  asm volatile("cp.async.wait_group 1;" ::: "memory")
#define CP_WAIT0()  asm volatile("cp.async.wait_group 0;" ::: "memory")

// ======================= B conversion (coalesced transpose, 96 blocks) =======================
// grid (12, 8): block transposes a 32n x 32k chunk. Phase 1: coalesced fp32
// reads over n. Phase 2: vectorized uint4 writes over k.
__global__ __launch_bounds__(256)
void conv_b_kernel(const float* __restrict__ Woff, const float* __restrict__ Wattn)
{
    __shared__ __nv_bfloat16 sHI[32][40];
    __shared__ __nv_bfloat16 sLO[32][40];

    const int nb = blockIdx.x;              // 0..11
    const int kb = blockIdx.y;              // 0..7
    const int nx = threadIdx.x & 31;
    const int ky = threadIdx.x >> 5;        // 0..7
    const int n  = nb * 32 + nx;
    const bool attn = (n >= 256);
    const float* src  = attn ? (Wattn + (n - 256)) : (Woff + n);
    const int    lds_ = attn ? 128 : 256;

    #pragma unroll
    for (int i = 0; i < 4; i++) {
        const int kl = i * 8 + ky;
        const float x = __ldg(src + (size_t)(kb * 32 + kl) * lds_);
        const __nv_bfloat16 h = __float2bfloat16(x);
        sHI[nx][kl] = h;
        sLO[nx][kl] = __float2bfloat16(x - __bfloat162float(h));
    }
    __syncthreads();

    if (threadIdx.x < 128) {
        const int n2 = threadIdx.x >> 2;    // 0..31
        const int v  = threadIdx.x & 3;     // 0..3
        const int kl = v * 8;
        const int gn = nb * 32 + n2;
        const int gk = kb * 32 + kl;
        const __nv_bfloat16* ph = &sHI[n2][kl];
        const __nv_bfloat16* pl = &sLO[n2][kl];
        uint4 uh, ul;
        uh.x = pack_bf2(ph[0], ph[1]); uh.y = pack_bf2(ph[2], ph[3]);
        uh.z = pack_bf2(ph[4], ph[5]); uh.w = pack_bf2(ph[6], ph[7]);
        ul.x = pack_bf2(pl[0], pl[1]); ul.y = pack_bf2(pl[2], pl[3]);
        ul.z = pack_bf2(pl[4], pl[5]); ul.w = pack_bf2(pl[6], pl[7]);
        *reinterpret_cast<uint4*>(g_bhi + (size_t)gn * EMBED + gk) = uh;
        *reinterpret_cast<uint4*>(g_blo + (size_t)gn * EMBED + gk) = ul;
    }
}

// ======================= mma.sync GEMM (M=64 tiles, cp.async B pipeline) =======================
// C[16000,384] = Q @ [W_off|W_attn]^T via split-bf16 (Ah*Bh + Ah*Bl + Al*Bh), fp32 acc.
// grid (250, 3): CTA tile 64(M) x 128(N), K = 256 chunked 4 x 64, 8 warps.
// A hi/lo split fused into (synchronous) staging; B chunks double-buffered via
// cp.async so chunk kc+1 streams in while chunk kc computes.
#define LDA    72
#define A_HI   0
#define A_LO   9216                 // 64*72*2
#define B_BUF  18432                // start of B double buffer
#define B_STG  36864                // one stage = hi(18432) + lo(18432)
#define B_LO_O 18432
#define SMT    92160
#define LDD    132

__global__ __launch_bounds__(256)
void mma_gemm_kernel(const float* __restrict__ Q,
                     const float* __restrict__ boff, const float* __restrict__ battn)
{
    extern __shared__ char smem[];
    const int tid  = threadIdx.x;
    const int wid  = tid >> 5;
    const int lane = tid & 31;
    const int bn   = blockIdx.y;
    const int rowg = blockIdx.x * 64;
    const uint32_t sb = smem_u32(smem);

    const int warp_m = (wid >> 1) * 16;     // 0,16,32,48
    const int warp_n = (wid & 1) * 64;      // 0,64

    // per-thread B staging coords (4 rows of 8 bf16, hi+lo each)
    const int brow_ = tid >> 3;             // base row 0..31 (+32 per r)
    const int bj_   = tid & 7;

    // issue B chunk 0 into stage 0
    {
        const uint32_t dst0 = sb + B_BUF;
        #pragma unroll
        for (int r = 0; r < 4; r++) {
            const int row = brow_ + r * 32;
            const uint32_t doff = (uint32_t)(row * LDA + bj_ * 8) * 2;
            const size_t bsrc = (size_t)(bn * 128 + row) * EMBED + bj_ * 8;
            CP_ASYNC16(dst0 + doff,           g_bhi + bsrc);
            CP_ASYNC16(dst0 + B_LO_O + doff,  g_blo + bsrc);
        }
        CP_COMMIT();
    }

    float acc[8][4];
    #pragma unroll
    for (int nj = 0; nj < 8; nj++)
        #pragma unroll
        for (int c = 0; c < 4; c++) acc[nj][c] = 0.f;

    for (int kc = 0; kc < 4; kc++) {
        const int k0 = kc * 64;
        __syncthreads();   // previous compute done: A smem + next B stage reusable

        // --- A: 64 rows x 64 k, fp32 -> bf16 hi/lo in-register (synchronous) ---
        #pragma unroll
        for (int r = 0; r < 2; r++) {
            const int s = tid + r * 256;
            const int row = s >> 3, j = s & 7;
            const uint32_t doff = (uint32_t)(row * LDA + j * 8) * 2;
            const float* asrc = Q + (size_t)(rowg + row) * EMBED + k0 + j * 8;
            const float4 a0 = __ldg(reinterpret_cast<const float4*>(asrc));
            const float4 a1 = __ldg(reinterpret_cast<const float4*>(asrc) + 1);
            const float av[8] = {a0.x, a0.y, a0.z, a0.w, a1.x, a1.y, a1.z, a1.w};
            __nv_bfloat16 hi[8], lo[8];
            #pragma unroll
            for (int t = 0; t < 8; t++) {
                hi[t] = __float2bfloat16(av[t]);
                lo[t] = __float2bfloat16(av[t] - __bfloat162float(hi[t]));
            }
            uint4 uh, ul;
            uh.x = pack_bf2(hi[0], hi[1]); uh.y = pack_bf2(hi[2], hi[3]);
            uh.z = pack_bf2(hi[4], hi[5]); uh.w = pack_bf2(hi[6], hi[7]);
            ul.x = pack_bf2(lo[0], lo[1]); ul.y = pack_bf2(lo[2], lo[3]);
            ul.z = pack_bf2(lo[4], lo[5]); ul.w = pack_bf2(lo[6], lo[7]);
            *reinterpret_cast<uint4*>(smem + A_HI + doff) = uh;
            *reinterpret_cast<uint4*>(smem + A_LO + doff) = ul;
        }

        // --- prefetch B chunk kc+1 into the other stage ---
        if (kc < 3) {
            const uint32_t dstn = sb + B_BUF + ((kc + 1) & 1) * B_STG;
            const int kn = (kc + 1) * 64;
            #pragma unroll
            for (int r = 0; r < 4; r++) {
                const int row = brow_ + r * 32;
                const uint32_t doff = (uint32_t)(row * LDA + bj_ * 8) * 2;
                const size_t bsrc = (size_t)(bn * 128 + row) * EMBED + kn + bj_ * 8;
                CP_ASYNC16(dstn + doff,          g_bhi + bsrc);
                CP_ASYNC16(dstn + B_LO_O + doff, g_blo + bsrc);
            }
            CP_COMMIT();
            CP_WAIT1();    // chunk kc arrived (one newer group may remain in flight)
        } else {
            CP_WAIT0();
        }
        __syncthreads();

        const uint32_t bbase = sb + B_BUF + (kc & 1) * B_STG;

        #pragma unroll
        for (int ks = 0; ks < 4; ks++) {
            const int kk = ks * 16;

            uint32_t ah[4], al[4];
            const int ar = warp_m + (lane & 15);
            const int ac = kk + ((lane >> 4) << 3);
            const uint32_t ad = sb + A_HI + (uint32_t)((ar * LDA + ac) << 1);
            ldsm4(ah[0], ah[1], ah[2], ah[3], ad);
            ldsm4(al[0], al[1], al[2], al[3], ad + (A_LO - A_HI));

            uint32_t bhf[4][4], blf[4][4];
            const int br = warp_n + (lane & 7) + ((lane >> 4) << 3);
            const int bc = kk + (((lane >> 3) & 1) << 3);
            #pragma unroll
            for (int g = 0; g < 4; g++) {
                const uint32_t bd = bbase + (uint32_t)(((br + g * 16) * LDA + bc) << 1);
                ldsm4(bhf[g][0], bhf[g][1], bhf[g][2], bhf[g][3], bd);
                ldsm4(blf[g][0], blf[g][1], blf[g][2], blf[g][3], bd + B_LO_O);
            }

            #pragma unroll
            for (int nj = 0; nj < 8; nj++) {
                const int g = nj >> 1, o = (nj & 1) * 2;
                mma16816(acc[nj], ah, &bhf[g][o]);
                mma16816(acc[nj], ah, &blf[g][o]);
                mma16816(acc[nj], al, &bhf[g][o]);
            }
        }
    }

    // ---- accumulators -> reused smem D tile [64][LDD] ----
    __syncthreads();
    float* sD = reinterpret_cast<float*>(smem);
    #pragma unroll
    for (int nj = 0; nj < 8; nj++) {
        const int r0 = warp_m + (lane >> 2);
        const int c0 = warp_n + nj * 8 + (lane & 3) * 2;
        *reinterpret_cast<float2*>(sD + r0 * LDD + c0)       = make_float2(acc[nj][0], acc[nj][1]);
        *reinterpret_cast<float2*>(sD + (r0 + 8) * LDD + c0) = make_float2(acc[nj][2], acc[nj][3]);
    }
    __syncthreads();

    // ---- epilogue: bias (+softmax for attn block) -> g_logits ----
    const int row = tid >> 2;              // 0..63
    const int cs  = (tid & 3) * 32;        // 0,32,64,96
    float* orow = g_logits + (size_t)(rowg + row) * NLOGIT + bn * 128 + cs;

    float f[32];
    #pragma unroll
    for (int j = 0; j < 32; j++) {
        const int c = cs + j;
        const float bias = (bn < 2) ? __ldg(boff + bn * 128 + c) : __ldg(battn + c);
        f[j] = sD[row * LDD + c] + bias;
    }
    if (bn == 2) {
        #pragma unroll
        for (int g = 0; g < 2; g++) {
            float mx = f[g * 16];
            #pragma unroll
            for (int j = 1; j < 16; j++) mx = fmaxf(mx, f[g * 16 + j]);
            float s = 0.f;
            #pragma unroll
            for (int j = 0; j < 16; j++) { f[g * 16 + j] = __expf(f[g * 16 + j] - mx); s += f[g * 16 + j]; }
            const float rs = __fdividef(1.f, s);
            #pragma unroll
            for (int j = 0; j < 16; j++) f[g * 16 + j] *= rs;
        }
    }
    #pragma unroll
    for (int j = 0; j < 32; j += 4)
        *reinterpret_cast<float4*>(orow + j) = make_float4(f[j], f[j+1], f[j+2], f[j+3]);
}

// ======================= sampling kernel (R7 configuration — frozen local optimum) =======================
__global__ __launch_bounds__(256, 6)
void sample_kernel(const float* __restrict__ value,
                   const float* __restrict__ refp,
                   float* __restrict__ out)
{
    constexpr int cW[4]  = {100, 50, 25, 13};
    constexpr int cVS[4] = {0, 10000, 12500, 13125};

    const int warp = (blockIdx.x << 3) + (threadIdx.x >> 5);
    const int lane = threadIdx.x & 31;

    const int q  = warp % LQ_;
    const int bh = warp / LQ_;
    const int b  = bh >> 3;
    const int h  = bh & 7;
    const int row = b * LQ_ + q;

    const float* lg = g_logits + (size_t)row * NLOGIT;
    const float4 rp = __ldg(reinterpret_cast<const float4*>(refp) + row);

    const int psub = lane >> 3;
    const int dgrp = lane & 7;

    const float2* offp = reinterpret_cast<const float2*>(lg) + h * 16 + psub;
    const float*  app  = lg + 256 + h * 16 + psub;

    float2 off[4];
    float  ap[4];
    #pragma unroll
    for (int it = 0; it < 4; it++) {
        off[it] = __ldg(offp + (it << 2));
        ap[it]  = __ldg(app  + (it << 2));
    }

    const float* vb = value + (size_t)b * LV_ * EMBED + h * HDIM + dgrp * 4;

    float4 acc0 = make_float4(0.f, 0.f, 0.f, 0.f);
    float4 acc1 = acc0;

    #pragma unroll
    for (int it = 0; it < 4; it++) {
        const int   W  = cW[it];
        const float Wf = (float)W;

        const float px = fmaf(fmaf(off[it].x, 0.125f * rp.z, rp.x), Wf, -0.5f);
        const float py = fmaf(fmaf(off[it].y, 0.125f * rp.w, rp.y), Wf, -0.5f);
        const float fx0 = floorf(px), fy0 = floorf(py);
        const float fx = px - fx0,    fy = py - fy0;
        const int x0 = (int)fx0, y0 = (int)fy0;

        const float gx = 1.f - fx, gy = 1.f - fy;
        const float w00 = ap[it] * gx * gy;
        const float w10 = ap[it] * fx * gy;
        const float w01 = ap[it] * gx * fy;
        const float w11 = ap[it] * fx * fy;

        const bool xin0 = (unsigned)x0       < (unsigned)W;
        const bool xin1 = (unsigned)(x0 + 1) < (unsigned)W;
        const bool yin0 = (unsigned)y0       < (unsigned)W;   // H == W
        const bool yin1 = (unsigned)(y0 + 1) < (unsigned)W;

        const float* vl = vb + (ptrdiff_t)cVS[it] * EMBED
                             + (ptrdiff_t)(y0 * W + x0) * EMBED;

        float4 v00 = make_float4(0.f,0.f,0.f,0.f);
        float4 v10 = v00, v01 = v00, v11 = v00;
        if (xin0 && yin0) v00 = *reinterpret_cast<const float4*>(vl);
        if (xin1 && yin0) v10 = *reinterpret_cast<const float4*>(vl + EMBED);
        if (xin0 && yin1) v01 = *reinterpret_cast<const float4*>(vl + W * EMBED);
        if (xin1 && yin1) v11 = *reinterpret_cast<const float4*>(vl + W * EMBED + EMBED);

        float4& acc = (it & 1) ? acc1 : acc0;
        acc.x = fmaf(w00, v00.x, fmaf(w10, v10.x, fmaf(w01, v01.x, fmaf(w11, v11.x, acc.x))));
        acc.y = fmaf(w00, v00.y, fmaf(w10, v10.y, fmaf(w01, v01.y, fmaf(w11, v11.y, acc.y))));
        acc.z = fmaf(w00, v00.z, fmaf(w10, v10.z, fmaf(w01, v01.z, fmaf(w11, v11.z, acc.z))));
        acc.w = fmaf(w00, v00.w, fmaf(w10, v10.w, fmaf(w01, v01.w, fmaf(w11, v11.w, acc.w))));
    }

    float4 acc;
    acc.x = acc0.x + acc1.x;
    acc.y = acc0.y + acc1.y;
    acc.z = acc0.z + acc1.z;
    acc.w = acc0.w + acc1.w;

    #pragma unroll
    for (int o = 8; o <= 16; o <<= 1) {
        acc.x += __shfl_xor_sync(0xffffffffu, acc.x, o);
        acc.y += __shfl_xor_sync(0xffffffffu, acc.y, o);
        acc.z += __shfl_xor_sync(0xffffffffu, acc.z, o);
        acc.w += __shfl_xor_sync(0xffffffffu, acc.w, o);
    }

    if (psub == 0) {
        *reinterpret_cast<float4*>(out + (size_t)row * EMBED + h * HDIM + dgrp * 4) = acc;
    }
}

// ---------------- launch ----------------
extern "C" void kernel_launch(void* const* d_in, const int* in_sizes, int n_in,
                              void* d_out, int out_size)
{
    (void)in_sizes; (void)n_in; (void)out_size;
    const float* query = (const float*)d_in[0];
    const float* refp  = (const float*)d_in[1];
    const float* value = (const float*)d_in[2];
    // d_in[3] = value_spatial_shapes (int64) — hardcoded
    const float* Woff  = (const float*)d_in[4];
    const float* boff  = (const float*)d_in[5];
    const float* Wattn = (const float*)d_in[6];
    const float* battn = (const float*)d_in[7];
    float* out = (float*)d_out;

    static bool attr_set = false;
    if (!attr_set) {
        cudaFuncSetAttribute(mma_gemm_kernel,
                             cudaFuncAttributeMaxDynamicSharedMemorySize, SMT);
        attr_set = true;
    }

    conv_b_kernel<<<dim3(NLOGIT / 32, 8), 256>>>(Woff, Wattn);
    mma_gemm_kernel<<<dim3(NROWS / 64, 3), 256, SMT>>>(query, boff, battn);
    sample_kernel<<<(BS_ * NHEADS * LQ_) / 8, 256>>>(value, refp, out);
}

// round 13
// speedup vs baseline: 1.3032x; 1.0021x over previous
#include <cuda_runtime.h>
#include <cuda_bf16.h>
#include <cstdint>
#include <math.h>

// ---------------- problem constants ----------------
#define BS_      16
#define LQ_      1000
#define NROWS    (BS_*LQ_)         // 16000
#define EMBED    256
#define NHEADS   8
#define HDIM     32
#define NLOGIT   384               // 256 offset cols + 128 attn-prob cols
#define LV_      13294

__device__ float g_logits[NROWS * NLOGIT];      // off(256) | softmaxed attn(128)
__device__ __nv_bfloat16 g_bhi[NLOGIT * EMBED]; // B^T split-hi [n][k]
__device__ __nv_bfloat16 g_blo[NLOGIT * EMBED]; // B^T split-lo

// ======================= helpers =======================
__device__ __forceinline__ uint32_t smem_u32(const void* p) {
    uint32_t a;
    asm("{ .reg .u64 t; cvta.to.shared.u64 t, %1; cvt.u32.u64 %0, t; }" : "=r"(a) : "l"(p));
    return a;
}

__device__ __forceinline__ void ldsm4(uint32_t& r0, uint32_t& r1, uint32_t& r2, uint32_t& r3,
                                      uint32_t addr) {
    asm volatile("ldmatrix.sync.aligned.m8n8.x4.shared.b16 {%0,%1,%2,%3}, [%4];"
                 : "=r"(r0), "=r"(r1), "=r"(r2), "=r"(r3) : "r"(addr));
}

__device__ __forceinline__ void mma16816(float* c, const uint32_t* a, const uint32_t* b) {
    asm volatile(
        "mma.sync.aligned.m16n8k16.row.col.f32.bf16.bf16.f32 "
        "{%0,%1,%2,%3}, {%4,%5,%6,%7}, {%8,%9}, {%0,%1,%2,%3};"
        : "+f"(c[0]), "+f"(c[1]), "+f"(c[2]), "+f"(c[3])
        : "r"(a[0]), "r"(a[1]), "r"(a[2]), "r"(a[3]), "r"(b[0]), "r"(b[1]));
}

__device__ __forceinline__ uint32_t pack_bf2(__nv_bfloat16 a, __nv_bfloat16 b) {
    return (uint32_t)__bfloat16_as_ushort(a) | ((uint32_t)__bfloat16_as_ushort(b) << 16);
}

// ======================= B conversion (coalesced transpose, 96 blocks) =======================
__global__ __launch_bounds__(256)
void conv_b_kernel(const float* __restrict__ Woff, const float* __restrict__ Wattn)
{
    __shared__ __nv_bfloat16 sHI[32][40];
    __shared__ __nv_bfloat16 sLO[32][40];

    const int nb = blockIdx.x;              // 0..11
    const int kb = blockIdx.y;              // 0..7
    const int nx = threadIdx.x & 31;
    const int ky = threadIdx.x >> 5;        // 0..7
    const int n  = nb * 32 + nx;
    const bool attn = (n >= 256);
    const float* src  = attn ? (Wattn + (n - 256)) : (Woff + n);
    const int    lds_ = attn ? 128 : 256;

    #pragma unroll
    for (int i = 0; i < 4; i++) {
        const int kl = i * 8 + ky;
        const float x = __ldg(src + (size_t)(kb * 32 + kl) * lds_);
        const __nv_bfloat16 h = __float2bfloat16(x);
        sHI[nx][kl] = h;
        sLO[nx][kl] = __float2bfloat16(x - __bfloat162float(h));
    }
    __syncthreads();

    if (threadIdx.x < 128) {
        const int n2 = threadIdx.x >> 2;    // 0..31
        const int v  = threadIdx.x & 3;     // 0..3
        const int kl = v * 8;
        const int gn = nb * 32 + n2;
        const int gk = kb * 32 + kl;
        const __nv_bfloat16* ph = &sHI[n2][kl];
        const __nv_bfloat16* pl = &sLO[n2][kl];
        uint4 uh, ul;
        uh.x = pack_bf2(ph[0], ph[1]); uh.y = pack_bf2(ph[2], ph[3]);
        uh.z = pack_bf2(ph[4], ph[5]); uh.w = pack_bf2(ph[6], ph[7]);
        ul.x = pack_bf2(pl[0], pl[1]); ul.y = pack_bf2(pl[2], pl[3]);
        ul.z = pack_bf2(pl[4], pl[5]); ul.w = pack_bf2(pl[6], pl[7]);
        *reinterpret_cast<uint4*>(g_bhi + (size_t)gn * EMBED + gk) = uh;
        *reinterpret_cast<uint4*>(g_blo + (size_t)gn * EMBED + gk) = ul;
    }
}

// ======================= mma.sync GEMM (M=64 tiles, 4 CTAs/SM) =======================
// C[16000,384] = Q @ [W_off|W_attn]^T via split-bf16 (Ah*Bh + Ah*Bl + Al*Bh), fp32 acc.
// grid (250, 3): CTA tile 64(M) x 128(N), K = 256 chunked 4 x 64, 8 warps.
// Single-buffered smem (55.3 KB) so 4 CTAs co-reside per SM: staging latency is
// hidden by cross-CTA interleave (R12 showed intra-CTA prefetch buys nothing —
// the kernel is occupancy-bound). Inner loop keeps B fragments short-lived to
// fit the 64-reg budget of __launch_bounds__(256, 4).
#define LDA    72
#define A_HI   0
#define A_LO   9216                 // 64*72*2
#define B_HI   18432
#define B_LO   36864
#define SMT    55296
#define LDD    132

__global__ __launch_bounds__(256, 4)
void mma_gemm_kernel(const float* __restrict__ Q,
                     const float* __restrict__ boff, const float* __restrict__ battn)
{
    extern __shared__ char smem[];
    const int tid  = threadIdx.x;
    const int wid  = tid >> 5;
    const int lane = tid & 31;
    const int bn   = blockIdx.y;
    const int rowg = blockIdx.x * 64;
    const uint32_t sb = smem_u32(smem);

    const int warp_m = (wid >> 1) * 16;     // 0,16,32,48
    const int warp_n = (wid & 1) * 64;      // 0,64

    float acc[8][4];
    #pragma unroll
    for (int nj = 0; nj < 8; nj++)
        #pragma unroll
        for (int c = 0; c < 4; c++) acc[nj][c] = 0.f;

    for (int kc = 0; kc < 4; kc++) {
        const int k0 = kc * 64;
        __syncthreads();

        // --- A: 64 rows x 64 k, fp32 -> bf16 hi/lo in-register ---
        #pragma unroll
        for (int r = 0; r < 2; r++) {
            const int s = tid + r * 256;
            const int row = s >> 3, j = s & 7;
            const uint32_t doff = (uint32_t)(row * LDA + j * 8) * 2;
            const float* asrc = Q + (size_t)(rowg + row) * EMBED + k0 + j * 8;
            const float4 a0 = __ldg(reinterpret_cast<const float4*>(asrc));
            const float4 a1 = __ldg(reinterpret_cast<const float4*>(asrc) + 1);
            const float av[8] = {a0.x, a0.y, a0.z, a0.w, a1.x, a1.y, a1.z, a1.w};
            __nv_bfloat16 hi[8], lo[8];
            #pragma unroll
            for (int t = 0; t < 8; t++) {
                hi[t] = __float2bfloat16(av[t]);
                lo[t] = __float2bfloat16(av[t] - __bfloat162float(hi[t]));
            }
            uint4 uh, ul;
            uh.x = pack_bf2(hi[0], hi[1]); uh.y = pack_bf2(hi[2], hi[3]);
            uh.z = pack_bf2(hi[4], hi[5]); uh.w = pack_bf2(hi[6], hi[7]);
            ul.x = pack_bf2(lo[0], lo[1]); ul.y = pack_bf2(lo[2], lo[3]);
            ul.z = pack_bf2(lo[4], lo[5]); ul.w = pack_bf2(lo[6], lo[7]);
            *reinterpret_cast<uint4*>(smem + A_HI + doff) = uh;
            *reinterpret_cast<uint4*>(smem + A_LO + doff) = ul;
        }
        // --- B: 128 n-rows x 64 k, pre-split bf16 ---
        #pragma unroll
        for (int r = 0; r < 4; r++) {
            const int s = tid + r * 256;
            const int row = s >> 3, j = s & 7;
            const uint32_t doff = (uint32_t)(row * LDA + j * 8) * 2;
            const size_t bsrc = (size_t)(bn * 128 + row) * EMBED + k0 + j * 8;
            *reinterpret_cast<uint4*>(smem + B_HI + doff) = *reinterpret_cast<const uint4*>(g_bhi + bsrc);
            *reinterpret_cast<uint4*>(smem + B_LO + doff) = *reinterpret_cast<const uint4*>(g_blo + bsrc);
        }
        __syncthreads();

        #pragma unroll
        for (int ks = 0; ks < 4; ks++) {
            const int kk = ks * 16;

            uint32_t ah[4], al[4];
            const int ar = warp_m + (lane & 15);
            const int ac = kk + ((lane >> 4) << 3);
            const uint32_t ad = sb + A_HI + (uint32_t)((ar * LDA + ac) << 1);
            ldsm4(ah[0], ah[1], ah[2], ah[3], ad);
            ldsm4(al[0], al[1], al[2], al[3], ad + (A_LO - A_HI));

            const int br = warp_n + (lane & 7) + ((lane >> 4) << 3);
            const int bc = kk + (((lane >> 3) & 1) << 3);
            #pragma unroll
            for (int g = 0; g < 4; g++) {
                // B fragments loaded per-group and consumed immediately (low live set)
                uint32_t bh[4], bl[4];
                const uint32_t bd = sb + B_HI + (uint32_t)(((br + g * 16) * LDA + bc) << 1);
                ldsm4(bh[0], bh[1], bh[2], bh[3], bd);
                ldsm4(bl[0], bl[1], bl[2], bl[3], bd + (B_LO - B_HI));

                mma16816(acc[g * 2],     ah, &bh[0]);
                mma16816(acc[g * 2],     ah, &bl[0]);
                mma16816(acc[g * 2],     al, &bh[0]);
                mma16816(acc[g * 2 + 1], ah, &bh[2]);
                mma16816(acc[g * 2 + 1], ah, &bl[2]);
                mma16816(acc[g * 2 + 1], al, &bh[2]);
            }
        }
    }

    // ---- accumulators -> reused smem D tile [64][LDD] ----
    __syncthreads();
    float* sD = reinterpret_cast<float*>(smem);
    #pragma unroll
    for (int nj = 0; nj < 8; nj++) {
        const int r0 = warp_m + (lane >> 2);
        const int c0 = warp_n + nj * 8 + (lane & 3) * 2;
        *reinterpret_cast<float2*>(sD + r0 * LDD + c0)       = make_float2(acc[nj][0], acc[nj][1]);
        *reinterpret_cast<float2*>(sD + (r0 + 8) * LDD + c0) = make_float2(acc[nj][2], acc[nj][3]);
    }
    __syncthreads();

    // ---- epilogue: bias (+softmax for attn block) -> g_logits ----
    const int row = tid >> 2;              // 0..63
    const int cs  = (tid & 3) * 32;        // 0,32,64,96
    float* orow = g_logits + (size_t)(rowg + row) * NLOGIT + bn * 128 + cs;

    float f[32];
    #pragma unroll
    for (int j = 0; j < 32; j++) {
        const int c = cs + j;
        const float bias = (bn < 2) ? __ldg(boff + bn * 128 + c) : __ldg(battn + c);
        f[j] = sD[row * LDD + c] + bias;
    }
    if (bn == 2) {
        #pragma unroll
        for (int g = 0; g < 2; g++) {
            float mx = f[g * 16];
            #pragma unroll
            for (int j = 1; j < 16; j++) mx = fmaxf(mx, f[g * 16 + j]);
            float s = 0.f;
            #pragma unroll
            for (int j = 0; j < 16; j++) { f[g * 16 + j] = __expf(f[g * 16 + j] - mx); s += f[g * 16 + j]; }
            const float rs = __fdividef(1.f, s);
            #pragma unroll
            for (int j = 0; j < 16; j++) f[g * 16 + j] *= rs;
        }
    }
    #pragma unroll
    for (int j = 0; j < 32; j += 4)
        *reinterpret_cast<float4*>(orow + j) = make_float4(f[j], f[j+1], f[j+2], f[j+3]);
}

// ======================= sampling kernel (R7 configuration — frozen local optimum) =======================
__global__ __launch_bounds__(256, 6)
void sample_kernel(const float* __restrict__ value,
                   const float* __restrict__ refp,
                   float* __restrict__ out)
{
    constexpr int cW[4]  = {100, 50, 25, 13};
    constexpr int cVS[4] = {0, 10000, 12500, 13125};

    const int warp = (blockIdx.x << 3) + (threadIdx.x >> 5);
    const int lane = threadIdx.x & 31;

    const int q  = warp % LQ_;
    const int bh = warp / LQ_;
    const int b  = bh >> 3;
    const int h  = bh & 7;
    const int row = b * LQ_ + q;

    const float* lg = g_logits + (size_t)row * NLOGIT;
    const float4 rp = __ldg(reinterpret_cast<const float4*>(refp) + row);

    const int psub = lane >> 3;
    const int dgrp = lane & 7;

    const float2* offp = reinterpret_cast<const float2*>(lg) + h * 16 + psub;
    const float*  app  = lg + 256 + h * 16 + psub;

    float2 off[4];
    float  ap[4];
    #pragma unroll
    for (int it = 0; it < 4; it++) {
        off[it] = __ldg(offp + (it << 2));
        ap[it]  = __ldg(app  + (it << 2));
    }

    const float* vb = value + (size_t)b * LV_ * EMBED + h * HDIM + dgrp * 4;

    float4 acc0 = make_float4(0.f, 0.f, 0.f, 0.f);
    float4 acc1 = acc0;

    #pragma unroll
    for (int it = 0; it < 4; it++) {
        const int   W  = cW[it];
        const float Wf = (float)W;

        const float px = fmaf(fmaf(off[it].x, 0.125f * rp.z, rp.x), Wf, -0.5f);
        const float py = fmaf(fmaf(off[it].y, 0.125f * rp.w, rp.y), Wf, -0.5f);
        const float fx0 = floorf(px), fy0 = floorf(py);
        const float fx = px - fx0,    fy = py - fy0;
        const int x0 = (int)fx0, y0 = (int)fy0;

        const float gx = 1.f - fx, gy = 1.f - fy;
        const float w00 = ap[it] * gx * gy;
        const float w10 = ap[it] * fx * gy;
        const float w01 = ap[it] * gx * fy;
        const float w11 = ap[it] * fx * fy;

        const bool xin0 = (unsigned)x0       < (unsigned)W;
        const bool xin1 = (unsigned)(x0 + 1) < (unsigned)W;
        const bool yin0 = (unsigned)y0       < (unsigned)W;   // H == W
        const bool yin1 = (unsigned)(y0 + 1) < (unsigned)W;

        const float* vl = vb + (ptrdiff_t)cVS[it] * EMBED
                             + (ptrdiff_t)(y0 * W + x0) * EMBED;

        float4 v00 = make_float4(0.f,0.f,0.f,0.f);
        float4 v10 = v00, v01 = v00, v11 = v00;
        if (xin0 && yin0) v00 = *reinterpret_cast<const float4*>(vl);
        if (xin1 && yin0) v10 = *reinterpret_cast<const float4*>(vl + EMBED);
        if (xin0 && yin1) v01 = *reinterpret_cast<const float4*>(vl + W * EMBED);
        if (xin1 && yin1) v11 = *reinterpret_cast<const float4*>(vl + W * EMBED + EMBED);

        float4& acc = (it & 1) ? acc1 : acc0;
        acc.x = fmaf(w00, v00.x, fmaf(w10, v10.x, fmaf(w01, v01.x, fmaf(w11, v11.x, acc.x))));
        acc.y = fmaf(w00, v00.y, fmaf(w10, v10.y, fmaf(w01, v01.y, fmaf(w11, v11.y, acc.y))));
        acc.z = fmaf(w00, v00.z, fmaf(w10, v10.z, fmaf(w01, v01.z, fmaf(w11, v11.z, acc.z))));
        acc.w = fmaf(w00, v00.w, fmaf(w10, v10.w, fmaf(w01, v01.w, fmaf(w11, v11.w, acc.w))));
    }

    float4 acc;
    acc.x = acc0.x + acc1.x;
    acc.y = acc0.y + acc1.y;
    acc.z = acc0.z + acc1.z;
    acc.w = acc0.w + acc1.w;

    #pragma unroll
    for (int o = 8; o <= 16; o <<= 1) {
        acc.x += __shfl_xor_sync(0xffffffffu, acc.x, o);
        acc.y += __shfl_xor_sync(0xffffffffu, acc.y, o);
        acc.z += __shfl_xor_sync(0xffffffffu, acc.z, o);
        acc.w += __shfl_xor_sync(0xffffffffu, acc.w, o);
    }

    if (psub == 0) {
        *reinterpret_cast<float4*>(out + (size_t)row * EMBED + h * HDIM + dgrp * 4) = acc;
    }
}

// ---------------- launch ----------------
extern "C" void kernel_launch(void* const* d_in, const int* in_sizes, int n_in,
                              void* d_out, int out_size)
{
    (void)in_sizes; (void)n_in; (void)out_size;
    const float* query = (const float*)d_in[0];
    const float* refp  = (const float*)d_in[1];
    const float* value = (const float*)d_in[2];
    // d_in[3] = value_spatial_shapes (int64) — hardcoded
    const float* Woff  = (const float*)d_in[4];
    const float* boff  = (const float*)d_in[5];
    const float* Wattn = (const float*)d_in[6];
    const float* battn = (const float*)d_in[7];
    float* out = (float*)d_out;

    static bool attr_set = false;
    if (!attr_set) {
        cudaFuncSetAttribute(mma_gemm_kernel,
                             cudaFuncAttributeMaxDynamicSharedMemorySize, SMT);
        attr_set = true;
    }

    conv_b_kernel<<<dim3(NLOGIT / 32, 8), 256>>>(Woff, Wattn);
    mma_gemm_kernel<<<dim3(NROWS / 64, 3), 256, SMT>>>(query, boff, battn);
    sample_kernel<<<(BS_ * NHEADS * LQ_) / 8, 256>>>(value, refp, out);
}